// round 3
// baseline (speedup 1.0000x reference)
#include <cuda_runtime.h>
#include <cstddef>

// ---------------------------------------------------------------------------
// BiMiniGRU: B=8, L=8192, C=D=256
//   proj: 6x GEMM [65536,256]x[256,256] + bias (+sigmoid on z,s)
//   scan: h[t] = (1-z)*h[t-1] + z*h~[t]  (fwd and time-reversed bwd)
//   out  = h_f * s_f + h_b * s_b
// ---------------------------------------------------------------------------

#define BSZ 8
#define LSZ 8192
#define DSZ 256
#define MSZ (BSZ * LSZ)        // 65536 rows
#define LC  128                // scan segment length
#define NSEG (LSZ / LC)        // 64 segments

// Scratch (allocation-free rule: __device__ globals)
// widx order: 0=z_f, 1=h~_f, 2=s_f, 3=z_b, 4=h~_b, 5=s_b
__device__ float g_proj[6][(size_t)MSZ * DSZ];
__device__ float g_segA[2 * BSZ * NSEG * DSZ];
__device__ float g_segB[2 * BSZ * NSEG * DSZ];
__device__ float g_carry[2 * BSZ * NSEG * DSZ];

struct GemmArgs {
    const float* W[6];
    const float* bias[6];
    const float* x;
};

__device__ __forceinline__ float sigmoidf_(float x) {
    return 1.0f / (1.0f + __expf(-x));
}

// ---------------------------------------------------------------------------
// Fused 6-way SGEMM: 128x128 block tile, BK=16, 8x8 per thread, reg prefetch.
// grid = (12, 512): blockIdx.x selects (weight, n-half), blockIdx.y the M tile.
// ---------------------------------------------------------------------------
__global__ __launch_bounds__(256, 2)
void gemm6_kernel(GemmArgs args) {
    const int widx = blockIdx.x >> 1;            // which of the 6 weights
    const int n0   = (blockIdx.x & 1) * 128;     // column offset inside weight
    const int m0   = blockIdx.y * 128;

    const float* __restrict__ X  = args.x;
    const float* __restrict__ Wp = args.W[widx];
    const float* __restrict__ bp = args.bias[widx];
    float* __restrict__ Out = g_proj[widx];

    __shared__ __align__(16) float As[16][128];  // [k][m] (transposed)
    __shared__ __align__(16) float Bs[16][128];  // [k][n]

    const int t  = threadIdx.x;
    const int tx = t & 15;    // n-dim
    const int ty = t >> 4;    // m-dim

    float acc[8][8];
    #pragma unroll
    for (int i = 0; i < 8; i++)
        #pragma unroll
        for (int j = 0; j < 8; j++) acc[i][j] = 0.0f;

    // ---- tile load helpers (2 float4 each per thread) ----
    // A tile: 128 rows x 16 cols; B tile: 16 rows x 128 cols
    auto ldgA = [&](int k0, float4* pa) {
        #pragma unroll
        for (int l = 0; l < 2; l++) {
            int lin = t + l * 256;
            int row = lin >> 2;
            int c4  = (lin & 3) * 4;
            pa[l] = *reinterpret_cast<const float4*>(
                X + (size_t)(m0 + row) * 256 + k0 + c4);
        }
    };
    auto ldgB = [&](int k0, float4* pb) {
        #pragma unroll
        for (int l = 0; l < 2; l++) {
            int lin = t + l * 256;
            int row = lin >> 5;
            int c4  = (lin & 31) * 4;
            pb[l] = *reinterpret_cast<const float4*>(
                Wp + (size_t)(k0 + row) * 256 + n0 + c4);
        }
    };
    auto stsA = [&](const float4* pa) {
        #pragma unroll
        for (int l = 0; l < 2; l++) {
            int lin = t + l * 256;
            int row = lin >> 2;
            int c4  = (lin & 3) * 4;
            As[c4 + 0][row] = pa[l].x;
            As[c4 + 1][row] = pa[l].y;
            As[c4 + 2][row] = pa[l].z;
            As[c4 + 3][row] = pa[l].w;
        }
    };
    auto stsB = [&](const float4* pb) {
        #pragma unroll
        for (int l = 0; l < 2; l++) {
            int lin = t + l * 256;
            int row = lin >> 5;
            int c4  = (lin & 31) * 4;
            *reinterpret_cast<float4*>(&Bs[row][c4]) = pb[l];
        }
    };
    auto compute = [&]() {
        #pragma unroll
        for (int kk = 0; kk < 16; kk++) {
            float ra[8], rb[8];
            *reinterpret_cast<float4*>(&ra[0]) =
                *reinterpret_cast<const float4*>(&As[kk][ty * 8]);
            *reinterpret_cast<float4*>(&ra[4]) =
                *reinterpret_cast<const float4*>(&As[kk][ty * 8 + 4]);
            *reinterpret_cast<float4*>(&rb[0]) =
                *reinterpret_cast<const float4*>(&Bs[kk][tx * 8]);
            *reinterpret_cast<float4*>(&rb[4]) =
                *reinterpret_cast<const float4*>(&Bs[kk][tx * 8 + 4]);
            #pragma unroll
            for (int i = 0; i < 8; i++)
                #pragma unroll
                for (int j = 0; j < 8; j++)
                    acc[i][j] = fmaf(ra[i], rb[j], acc[i][j]);
        }
    };

    // ---- mainloop with register prefetch double-buffering ----
    float4 pa[2], pb[2];
    ldgA(0, pa); ldgB(0, pb);
    stsA(pa); stsB(pb);
    __syncthreads();
    for (int k0 = 16; k0 < 256; k0 += 16) {
        ldgA(k0, pa); ldgB(k0, pb);   // issue global loads early
        compute();
        __syncthreads();
        stsA(pa); stsB(pb);
        __syncthreads();
    }
    compute();

    // ---- epilogue: +bias, activation, store ----
    const bool do_sig = (widx % 3) != 1;   // z and s get sigmoid, h~ raw
    float bias_r[8];
    #pragma unroll
    for (int j = 0; j < 8; j++) bias_r[j] = bp[n0 + tx * 8 + j];

    #pragma unroll
    for (int i = 0; i < 8; i++) {
        int row = m0 + ty * 8 + i;
        #pragma unroll
        for (int j = 0; j < 8; j += 4) {
            float4 v;
            float* vp = &v.x;
            #pragma unroll
            for (int q = 0; q < 4; q++) {
                float val = acc[i][j + q] + bias_r[j + q];
                if (do_sig) val = sigmoidf_(val);
                vp[q] = val;
            }
            *reinterpret_cast<float4*>(
                Out + (size_t)row * 256 + n0 + tx * 8 + j) = v;
        }
    }
}

// ---------------------------------------------------------------------------
// Scan pass 1: per (dir, b, seg) x d, compose the segment's affine map
//   (A, Bc) <- (A*a, a*Bc + b) with a = 1-z, b = z*h~
// grid (NSEG, BSZ, 2), block DSZ
// ---------------------------------------------------------------------------
__global__ void scan_pass1() {
    const int d   = threadIdx.x;
    const int seg = blockIdx.x;
    const int b   = blockIdx.y;
    const int dir = blockIdx.z;
    const float* __restrict__ Z = g_proj[3 * dir + 0];
    const float* __restrict__ H = g_proj[3 * dir + 1];

    float A = 1.0f, Bc = 0.0f;
    #pragma unroll 8
    for (int i = 0; i < LC; i++) {
        int p  = seg * LC + i;
        int tt = dir ? (LSZ - 1 - p) : p;
        size_t idx = ((size_t)b * LSZ + tt) * DSZ + d;
        float z = Z[idx], ht = H[idx];
        float a = 1.0f - z;
        A  = A * a;
        Bc = fmaf(a, Bc, z * ht);
    }
    size_t o = (((size_t)dir * BSZ + b) * NSEG + seg) * DSZ + d;
    g_segA[o] = A;
    g_segB[o] = Bc;
}

// ---------------------------------------------------------------------------
// Scan pass 2: sequential combine across the 64 segments per (dir,b,d),
// recording the carry-in h at each segment boundary. grid (BSZ,2), block DSZ
// ---------------------------------------------------------------------------
__global__ void scan_pass2(const float* __restrict__ h0f,
                           const float* __restrict__ h0b) {
    const int d   = threadIdx.x;
    const int b   = blockIdx.x;
    const int dir = blockIdx.y;
    float h = dir ? h0b[d] : h0f[d];
    size_t base = (((size_t)dir * BSZ + b) * NSEG) * DSZ + d;
    for (int s = 0; s < NSEG; s++) {
        size_t o = base + (size_t)s * DSZ;
        g_carry[o] = h;
        h = fmaf(g_segA[o], h, g_segB[o]);
    }
}

// ---------------------------------------------------------------------------
// Scan pass 3: replay each segment from its carry, apply s-gate, write/accum
// output. dir=0 writes, dir=1 accumulates (launched sequentially).
// grid (NSEG, BSZ), block DSZ
// ---------------------------------------------------------------------------
__global__ void scan_pass3(float* __restrict__ out, int dir) {
    const int d   = threadIdx.x;
    const int seg = blockIdx.x;
    const int b   = blockIdx.y;
    const float* __restrict__ Z = g_proj[3 * dir + 0];
    const float* __restrict__ H = g_proj[3 * dir + 1];
    const float* __restrict__ S = g_proj[3 * dir + 2];

    size_t o = (((size_t)dir * BSZ + b) * NSEG + seg) * DSZ + d;
    float h = g_carry[o];
    #pragma unroll 8
    for (int i = 0; i < LC; i++) {
        int p  = seg * LC + i;
        int tt = dir ? (LSZ - 1 - p) : p;
        size_t idx = ((size_t)b * LSZ + tt) * DSZ + d;
        float z = Z[idx], ht = H[idx];
        h = fmaf(1.0f - z, h, z * ht);
        float v = h * S[idx];
        if (dir) out[idx] += v;
        else     out[idx]  = v;
    }
}

// ---------------------------------------------------------------------------
// Launch
// Input order (metadata): 0 xs, 1 Wh1, 2 bh1, 3 Wz1, 4 bz1, 5 Ws1, 6 bs1,
//   7 h01, 8 Wh_1, 9 bh_1, 10 Wz_1, 11 bz_1, 12 Ws_1, 13 bs_1, 14 h0_1
// ---------------------------------------------------------------------------
extern "C" void kernel_launch(void* const* d_in, const int* in_sizes, int n_in,
                              void* d_out, int out_size) {
    GemmArgs ga;
    ga.x = (const float*)d_in[0];
    // widx: 0=z_f(Wz1), 1=h_f(Wh1), 2=s_f(Ws1), 3=z_b(Wz_1), 4=h_b(Wh_1), 5=s_b(Ws_1)
    ga.W[0] = (const float*)d_in[3];   ga.bias[0] = (const float*)d_in[4];
    ga.W[1] = (const float*)d_in[1];   ga.bias[1] = (const float*)d_in[2];
    ga.W[2] = (const float*)d_in[5];   ga.bias[2] = (const float*)d_in[6];
    ga.W[3] = (const float*)d_in[10];  ga.bias[3] = (const float*)d_in[11];
    ga.W[4] = (const float*)d_in[8];   ga.bias[4] = (const float*)d_in[9];
    ga.W[5] = (const float*)d_in[12];  ga.bias[5] = (const float*)d_in[13];

    dim3 gg(12, MSZ / 128);
    gemm6_kernel<<<gg, 256>>>(ga);

    scan_pass1<<<dim3(NSEG, BSZ, 2), DSZ>>>();
    scan_pass2<<<dim3(BSZ, 2), DSZ>>>((const float*)d_in[7],
                                      (const float*)d_in[14]);
    scan_pass3<<<dim3(NSEG, BSZ), DSZ>>>((float*)d_out, 0);
    scan_pass3<<<dim3(NSEG, BSZ), DSZ>>>((float*)d_out, 1);
}

// round 5
// speedup vs baseline: 1.8636x; 1.8636x over previous
#include <cuda_runtime.h>
#include <cuda_bf16.h>
#include <cstdint>
#include <cstddef>

// ---------------------------------------------------------------------------
// BiMiniGRU: B=8, L=8192, C=D=256
//   proj: 6x GEMM [65536,256]x[256,256] + bias (+sigmoid on z,s)
//         -> bf16x3 split on mma.sync (HMMA, plain PTX: compute_103-legal)
//   scan: h[t] = (1-z)*h[t-1] + z*h~[t]  (fwd and reversed bwd)
//   out  = h_f * s_f + h_b * s_b
// ---------------------------------------------------------------------------

#define BSZ 8
#define LSZ 8192
#define DSZ 256
#define MSZ (BSZ * LSZ)          // 65536
#define LC  64                   // scan segment length
#define NSEG (LSZ / LC)          // 128

// GEMM tiling
#define KCH 64                   // K chunk per stage
#define STG_SZ 65536             // bytes per stage (Ahi/Alo/Bhi/Blo 16KB each)
#define OFF_AHI 0
#define OFF_ALO 16384
#define OFF_BHI 32768
#define OFF_BLO 49152
#define GEMM_SMEM (2 * STG_SZ)   // 131072

#define SW128(o) ((o) ^ (((o) >> 3) & 0x70))

// ---------------------------------------------------------------------------
// Scratch (allocation-free rule: __device__ globals)
// widx order: 0=z_f, 1=h~_f, 2=s_f, 3=z_b, 4=h~_b, 5=s_b
// ---------------------------------------------------------------------------
__device__ float g_proj[6][(size_t)MSZ * DSZ];
__device__ __align__(16) __nv_bfloat16 g_xhi[(size_t)MSZ * DSZ];
__device__ __align__(16) __nv_bfloat16 g_xlo[(size_t)MSZ * DSZ];
__device__ __align__(16) __nv_bfloat16 g_wThi[6][DSZ * DSZ];
__device__ __align__(16) __nv_bfloat16 g_wTlo[6][DSZ * DSZ];
__device__ float g_segA[2 * BSZ * NSEG * DSZ];
__device__ float g_segB[2 * BSZ * NSEG * DSZ];
__device__ float g_carry[2 * BSZ * NSEG * DSZ];

// ---------------------------------------------------------------------------
// PTX helpers (plain PTX only: sm_80-era ops, legal at compute_103)
// ---------------------------------------------------------------------------
__device__ __forceinline__ uint32_t smem_u32(const void* p) {
    uint32_t a;
    asm("{ .reg .u64 t; cvta.to.shared.u64 t, %1; cvt.u32.u64 %0, t; }"
        : "=r"(a) : "l"(p));
    return a;
}

#define CP16(dst, src) asm volatile( \
    "cp.async.cg.shared.global [%0], [%1], 16;" :: "r"(dst), "l"(src))
#define CP_COMMIT() asm volatile("cp.async.commit_group;" ::: "memory")
#define CP_WAIT(n)  asm volatile("cp.async.wait_group %0;" :: "n"(n) : "memory")

#define LDSM_X4(r, addr) asm volatile( \
    "ldmatrix.sync.aligned.m8n8.x4.shared.b16 {%0,%1,%2,%3}, [%4];" \
    : "=r"((r)[0]), "=r"((r)[1]), "=r"((r)[2]), "=r"((r)[3]) : "r"(addr))
#define LDSM_X2(r, addr) asm volatile( \
    "ldmatrix.sync.aligned.m8n8.x2.shared.b16 {%0,%1}, [%2];" \
    : "=r"((r)[0]), "=r"((r)[1]) : "r"(addr))

#define MMA_BF16(cc, a, b) asm volatile( \
    "mma.sync.aligned.m16n8k16.row.col.f32.bf16.bf16.f32 " \
    "{%0,%1,%2,%3}, {%4,%5,%6,%7}, {%8,%9}, {%0,%1,%2,%3};" \
    : "+f"((cc)[0]), "+f"((cc)[1]), "+f"((cc)[2]), "+f"((cc)[3]) \
    : "r"((a)[0]), "r"((a)[1]), "r"((a)[2]), "r"((a)[3]), \
      "r"((b)[0]), "r"((b)[1]))

__device__ __forceinline__ void split2(float v, __nv_bfloat16& h, __nv_bfloat16& l) {
    h = __float2bfloat16(v);
    l = __float2bfloat16(v - __bfloat162float(h));
}
__device__ __forceinline__ uint32_t pack2(__nv_bfloat16 a, __nv_bfloat16 b) {
    __nv_bfloat162 t; t.x = a; t.y = b;
    return *reinterpret_cast<uint32_t*>(&t);
}

// ---------------------------------------------------------------------------
// Precompute: x -> bf16 hi/lo
// ---------------------------------------------------------------------------
__global__ void split_x(const float4* __restrict__ x) {
    size_t i = (size_t)blockIdx.x * blockDim.x + threadIdx.x;
    float4 v = x[i];
    __nv_bfloat16 h0, h1, h2, h3, l0, l1, l2, l3;
    split2(v.x, h0, l0); split2(v.y, h1, l1);
    split2(v.z, h2, l2); split2(v.w, h3, l3);
    uint2 uh, ul;
    uh.x = pack2(h0, h1); uh.y = pack2(h2, h3);
    ul.x = pack2(l0, l1); ul.y = pack2(l2, l3);
    reinterpret_cast<uint2*>(g_xhi)[i] = uh;
    reinterpret_cast<uint2*>(g_xlo)[i] = ul;
}

// Precompute: W^T (n-major rows of k) bf16 hi/lo per weight
struct WPtrs { const float* W[6]; };
__global__ void prep_w(WPtrs wp) {
    int widx = blockIdx.x;
    int n = blockIdx.y;
    int k = threadIdx.x;
    float v = wp.W[widx][(size_t)k * DSZ + n];
    __nv_bfloat16 h, l;
    split2(v, h, l);
    g_wThi[widx][n * DSZ + k] = h;
    g_wTlo[widx][n * DSZ + k] = l;
}

// ---------------------------------------------------------------------------
// HMMA GEMM: grid (12, 512): x = weight*2 + n-half, y = m tile.
// 256 threads = 8 warps in 2(m) x 4(n); warp tile 64x32.
// ---------------------------------------------------------------------------
struct BiasPtrs { const float* b[6]; };

__global__ __launch_bounds__(256, 1)
void gemm6_mma(BiasPtrs gb) {
    extern __shared__ __align__(128) char sm[];
    uint32_t sbase = smem_u32(sm);

    const int widx = blockIdx.x >> 1;
    const int n0   = (blockIdx.x & 1) * 128;
    const int m0   = blockIdx.y * 128;
    const int t    = threadIdx.x;
    const int lane = t & 31;
    const int wid  = t >> 5;
    const int wm   = (wid & 1) * 64;
    const int wn   = (wid >> 1) * 32;

    const __nv_bfloat16* __restrict__ Ah = g_xhi;
    const __nv_bfloat16* __restrict__ Al = g_xlo;
    const __nv_bfloat16* __restrict__ Bh = g_wThi[widx];
    const __nv_bfloat16* __restrict__ Bl = g_wTlo[widx];

    float c[4][4][4];
    #pragma unroll
    for (int mi = 0; mi < 4; mi++)
        #pragma unroll
        for (int ni = 0; ni < 4; ni++)
            #pragma unroll
            for (int q = 0; q < 4; q++) c[mi][ni][q] = 0.0f;

    // ---- async chunk loader: 4 x 16B per buffer per thread ----
    auto load_chunk = [&](int kc, int s) {
        uint32_t so = sbase + s * STG_SZ;
        #pragma unroll
        for (int it = 0; it < 4; it++) {
            int seg = t + it * 256;
            int row = seg >> 3;          // 0..127
            int c16 = seg & 7;           // 16B unit within 128B row
            uint32_t sw = SW128((uint32_t)(row * 128 + c16 * 16));
            size_t ga = (size_t)(m0 + row) * DSZ + kc + c16 * 8;
            size_t gbp = (size_t)(n0 + row) * DSZ + kc + c16 * 8;
            CP16(so + OFF_AHI + sw, Ah + ga);
            CP16(so + OFF_ALO + sw, Al + ga);
            CP16(so + OFF_BHI + sw, Bh + gbp);
            CP16(so + OFF_BLO + sw, Bl + gbp);
        }
    };

    auto compute_stage = [&](int s) {
        uint32_t so = sbase + s * STG_SZ;
        const int g = lane >> 3, r = lane & 7;
        #pragma unroll
        for (int ks = 0; ks < KCH / 16; ks++) {
            // A frag lane addr: m = wm + (g&1)*8 + r, k = ks*16 + (g>>1)*8
            uint32_t aoff = SW128((uint32_t)(
                (wm + (g & 1) * 8 + r) * 128 + (ks * 16 + (g >> 1) * 8) * 2));
            // B frag lane addr: n = wn + r, k = ks*16 + (g&1)*8
            uint32_t boff = SW128((uint32_t)(
                (wn + r) * 128 + (ks * 16 + (g & 1) * 8) * 2));

            uint32_t ah[4][4], al[4][4], bh[4][2], bl[4][2];
            #pragma unroll
            for (int mi = 0; mi < 4; mi++) {
                LDSM_X4(ah[mi], so + OFF_AHI + aoff + mi * 2048);
                LDSM_X4(al[mi], so + OFF_ALO + aoff + mi * 2048);
            }
            #pragma unroll
            for (int ni = 0; ni < 4; ni++) {
                LDSM_X2(bh[ni], so + OFF_BHI + boff + ni * 1024);
                LDSM_X2(bl[ni], so + OFF_BLO + boff + ni * 1024);
            }
            #pragma unroll
            for (int mi = 0; mi < 4; mi++)
                #pragma unroll
                for (int ni = 0; ni < 4; ni++) {
                    MMA_BF16(c[mi][ni], ah[mi], bh[ni]);   // hi*hi
                    MMA_BF16(c[mi][ni], ah[mi], bl[ni]);   // hi*lo
                    MMA_BF16(c[mi][ni], al[mi], bh[ni]);   // lo*hi
                }
        }
    };

    // ---- 2-stage pipeline over 4 K-chunks ----
    load_chunk(0, 0);
    CP_COMMIT();
    #pragma unroll
    for (int ch = 0; ch < 4; ch++) {
        if (ch < 3) { load_chunk((ch + 1) * KCH, (ch + 1) & 1); CP_COMMIT(); }
        if (ch < 3) { CP_WAIT(1); } else { CP_WAIT(0); }
        __syncthreads();
        compute_stage(ch & 1);
        __syncthreads();
    }

    // ---- epilogue ----
    const bool do_sig = (widx % 3) != 1;   // z, s sigmoid; h~ raw
    const float* __restrict__ bias = gb.b[widx];
    float* __restrict__ Out = g_proj[widx];

    #pragma unroll
    for (int ni = 0; ni < 4; ni++) {
        const int col = n0 + wn + ni * 8 + (lane & 3) * 2;
        const float2 bb = *reinterpret_cast<const float2*>(bias + col);
        #pragma unroll
        for (int mi = 0; mi < 4; mi++) {
            const int row = m0 + wm + mi * 16 + (lane >> 2);
            float v0 = c[mi][ni][0] + bb.x;
            float v1 = c[mi][ni][1] + bb.y;
            float v2 = c[mi][ni][2] + bb.x;
            float v3 = c[mi][ni][3] + bb.y;
            if (do_sig) {
                v0 = 1.0f / (1.0f + __expf(-v0));
                v1 = 1.0f / (1.0f + __expf(-v1));
                v2 = 1.0f / (1.0f + __expf(-v2));
                v3 = 1.0f / (1.0f + __expf(-v3));
            }
            float2 p0; p0.x = v0; p0.y = v1;
            float2 p1; p1.x = v2; p1.y = v3;
            *reinterpret_cast<float2*>(Out + (size_t)row * DSZ + col) = p0;
            *reinterpret_cast<float2*>(Out + (size_t)(row + 8) * DSZ + col) = p1;
        }
    }
}

// ---------------------------------------------------------------------------
// Scan pass 1: per (dir,b,seg) x d, compose segment affine map
// ---------------------------------------------------------------------------
__global__ void scan_pass1() {
    const int d   = threadIdx.x;
    const int seg = blockIdx.x;
    const int b   = blockIdx.y;
    const int dir = blockIdx.z;
    const float* __restrict__ Z = g_proj[3 * dir + 0];
    const float* __restrict__ H = g_proj[3 * dir + 1];

    float A = 1.0f, Bc = 0.0f;
    #pragma unroll 8
    for (int i = 0; i < LC; i++) {
        int p  = seg * LC + i;
        int tt = dir ? (LSZ - 1 - p) : p;
        size_t idx = ((size_t)b * LSZ + tt) * DSZ + d;
        float z = Z[idx], ht = H[idx];
        float a = 1.0f - z;
        A  = A * a;
        Bc = fmaf(a, Bc, z * ht);
    }
    size_t o = (((size_t)dir * BSZ + b) * NSEG + seg) * DSZ + d;
    g_segA[o] = A;
    g_segB[o] = Bc;
}

// ---------------------------------------------------------------------------
// Scan pass 2: sequential combine over NSEG segments; register-batched.
// ---------------------------------------------------------------------------
__global__ void scan_pass2(const float* __restrict__ h0f,
                           const float* __restrict__ h0b) {
    const int d   = threadIdx.x;
    const int b   = blockIdx.x;
    const int dir = blockIdx.y;
    float h = dir ? h0b[d] : h0f[d];
    size_t base = (((size_t)dir * BSZ + b) * NSEG) * DSZ + d;
    for (int sc = 0; sc < NSEG / 16; sc++) {
        float rA[16], rB[16];
        #pragma unroll
        for (int s = 0; s < 16; s++) {
            size_t o = base + (size_t)(sc * 16 + s) * DSZ;
            rA[s] = g_segA[o];
            rB[s] = g_segB[o];
        }
        #pragma unroll
        for (int s = 0; s < 16; s++) {
            size_t o = base + (size_t)(sc * 16 + s) * DSZ;
            g_carry[o] = h;
            h = fmaf(rA[s], h, rB[s]);
        }
    }
}

// ---------------------------------------------------------------------------
// Scan out: both directions fused; fwd contribution staged in SMEM (64KB).
// ---------------------------------------------------------------------------
__global__ void scan_out(float* __restrict__ out) {
    extern __shared__ float sv[];
    const int d   = threadIdx.x;
    const int seg = blockIdx.x;
    const int b   = blockIdx.y;
    const float* __restrict__ Zf = g_proj[0];
    const float* __restrict__ Hf = g_proj[1];
    const float* __restrict__ Sf = g_proj[2];
    const float* __restrict__ Zb = g_proj[3];
    const float* __restrict__ Hb = g_proj[4];
    const float* __restrict__ Sb = g_proj[5];

    size_t rowbase = ((size_t)b * LSZ + (size_t)seg * LC) * DSZ + d;

    // forward
    float h = g_carry[(((size_t)0 * BSZ + b) * NSEG + seg) * DSZ + d];
    #pragma unroll 4
    for (int i = 0; i < LC; i++) {
        size_t idx = rowbase + (size_t)i * DSZ;
        float z = Zf[idx];
        h = fmaf(1.0f - z, h, z * Hf[idx]);
        sv[i * DSZ + d] = h * Sf[idx];
    }
    // backward (bwd segment NSEG-1-seg covers these rows, reversed)
    const int sb = NSEG - 1 - seg;
    float hb = g_carry[(((size_t)BSZ + b) * NSEG + sb) * DSZ + d];
    #pragma unroll 4
    for (int j = 0; j < LC; j++) {
        int i = LC - 1 - j;
        size_t idx = rowbase + (size_t)i * DSZ;
        float z = Zb[idx];
        hb = fmaf(1.0f - z, hb, z * Hb[idx]);
        out[idx] = sv[i * DSZ + d] + hb * Sb[idx];
    }
}

// ---------------------------------------------------------------------------
// Launch. Inputs: 0 xs, 1 Wh1, 2 bh1, 3 Wz1, 4 bz1, 5 Ws1, 6 bs1, 7 h01,
//   8 Wh_1, 9 bh_1, 10 Wz_1, 11 bz_1, 12 Ws_1, 13 bs_1, 14 h0_1
// ---------------------------------------------------------------------------
extern "C" void kernel_launch(void* const* d_in, const int* in_sizes, int n_in,
                              void* d_out, int out_size) {
    static bool attr_done = false;
    if (!attr_done) {
        cudaFuncSetAttribute(gemm6_mma,
                             cudaFuncAttributeMaxDynamicSharedMemorySize, GEMM_SMEM);
        cudaFuncSetAttribute(scan_out,
                             cudaFuncAttributeMaxDynamicSharedMemorySize, LC * DSZ * 4);
        attr_done = true;
    }

    // widx: 0=z_f(Wz1), 1=h_f(Wh1), 2=s_f(Ws1), 3=z_b(Wz_1), 4=h_b(Wh_1), 5=s_b(Ws_1)
    WPtrs wp;
    wp.W[0] = (const float*)d_in[3];
    wp.W[1] = (const float*)d_in[1];
    wp.W[2] = (const float*)d_in[5];
    wp.W[3] = (const float*)d_in[10];
    wp.W[4] = (const float*)d_in[8];
    wp.W[5] = (const float*)d_in[12];
    BiasPtrs bp;
    bp.b[0] = (const float*)d_in[4];
    bp.b[1] = (const float*)d_in[2];
    bp.b[2] = (const float*)d_in[6];
    bp.b[3] = (const float*)d_in[11];
    bp.b[4] = (const float*)d_in[9];
    bp.b[5] = (const float*)d_in[13];

    split_x<<<(size_t)MSZ * DSZ / 4 / 256, 256>>>((const float4*)d_in[0]);
    prep_w<<<dim3(6, 256), 256>>>(wp);
    gemm6_mma<<<dim3(12, MSZ / 128), 256, GEMM_SMEM>>>(bp);

    scan_pass1<<<dim3(NSEG, BSZ, 2), DSZ>>>();
    scan_pass2<<<dim3(BSZ, 2), DSZ>>>((const float*)d_in[7], (const float*)d_in[14]);
    scan_out<<<dim3(NSEG, BSZ), DSZ, LC * DSZ * 4>>>((float*)d_out);
}